// round 2
// baseline (speedup 1.0000x reference)
#include <cuda_runtime.h>
#include <cuda_bf16.h>

// PWC-Net 9x9 correlation + LeakyReLU(0.1), fp32.
// feat1, feat2: [8, 256, 80, 160]; out: [8, 81, 80, 160]
// out[n, dy*9+dx, y, x] = leaky( (1/256) * sum_c f1[n,c,y,x] * f2pad[n,c,y+dy,x+dx] )
// f2pad: 4-wide zero padding on H and W.
//
// Grid decomposition: each block handles a 32x16 pixel tile for ONE batch n and
// ONE dy-group g (dy = 3g..3g+2, 27 output channels). 600 blocks total.

#define NN 8
#define CC 256
#define HH 80
#define WW 160
#define KC 8          // channels per smem chunk
#define TY 16         // pixel rows per block
#define NDY 3         // dy values per block (g selects which 3)
#define F2ROWS (TY + NDY - 1)   // 18
#define F2PITCH 40              // 32 pixel cols + 8 halo

__global__ __launch_bounds__(128)
void corr_kernel(const float* __restrict__ f1,
                 const float* __restrict__ f2,
                 float* __restrict__ out)
{
    __shared__ float f1s[KC * TY * 32];          // [c][j][i]   16 KB
    __shared__ float f2s[KC * F2ROWS * F2PITCH]; // [c][r][i]   23 KB

    const int tx = threadIdx.x;            // 0..7  -> 4 pixels each along x
    const int ty = threadIdx.y;            // 0..15 -> pixel row
    const int t  = ty * 8 + tx;            // 0..127

    const int x0 = blockIdx.x * 32;        // 5 tiles cover W=160
    const int g  = blockIdx.y % 3;         // dy group (fast-varying after x for L2 reuse)
    const int y0 = (blockIdx.y / 3) * TY;  // 5 tiles cover H=80
    const int n  = blockIdx.z;

    const float* f1n = f1 + (size_t)n * CC * HH * WW;
    const float* f2n = f2 + (size_t)n * CC * HH * WW;

    const int y  = y0 + ty;
    const int xb = x0 + tx * 4;

    const float inv_c = 1.0f / 256.0f;

    float acc[NDY][4][9];
    #pragma unroll
    for (int q = 0; q < NDY; q++)
        #pragma unroll
        for (int px = 0; px < 4; px++)
            #pragma unroll
            for (int dx = 0; dx < 9; dx++)
                acc[q][px][dx] = 0.0f;

    const int ybase = y0 + 3 * g - 4;      // global f2 row for smem r=0

    for (int cc = 0; cc < CC; cc += KC) {
        __syncthreads();

        // ---- fill f1s: KC*TY rows of 32 floats = 1024 float4, 8 per thread
        #pragma unroll
        for (int k = t; k < KC * TY * 8; k += 128) {
            const int c   = k >> 7;          // / (TY*8)
            const int rem = k & 127;
            const int j   = rem >> 3;
            const int i4  = rem & 7;
            const float4 v = *(const float4*)(
                f1n + ((size_t)(cc + c) * HH + (y0 + j)) * WW + x0 + i4 * 4);
            *(float4*)&f1s[(c * TY + j) * 32 + i4 * 4] = v;
        }

        // ---- fill f2s: KC * 18 rows of 40 floats = 1440 float4 (zero-padded OOB)
        for (int k = t; k < KC * F2ROWS * 10; k += 128) {
            const int c   = k / (F2ROWS * 10);
            const int rem = k - c * (F2ROWS * 10);
            const int r   = rem / 10;
            const int i4  = rem - r * 10;
            const int gy  = ybase + r;
            const int gx  = x0 - 4 + i4 * 4;
            float4 v = make_float4(0.f, 0.f, 0.f, 0.f);
            // OOB only occurs as whole float4s (gx = -4 at left edge, 160 at right)
            if (gy >= 0 && gy < HH && gx >= 0 && gx + 3 < WW) {
                v = *(const float4*)(f2n + ((size_t)(cc + c) * HH + gy) * WW + gx);
            }
            *(float4*)&f2s[(c * F2ROWS + r) * F2PITCH + i4 * 4] = v;
        }

        __syncthreads();

        #pragma unroll 2
        for (int c = 0; c < KC; c++) {
            const float4 a4 = *(const float4*)&f1s[(c * TY + ty) * 32 + tx * 4];
            const float av[4] = {a4.x, a4.y, a4.z, a4.w};
            #pragma unroll
            for (int q = 0; q < NDY; q++) {
                const float* wr = &f2s[(c * F2ROWS + ty + q) * F2PITCH + tx * 4];
                const float4 w0 = *(const float4*)(wr);
                const float4 w1 = *(const float4*)(wr + 4);
                const float4 w2 = *(const float4*)(wr + 8);
                const float w[12] = {w0.x, w0.y, w0.z, w0.w,
                                     w1.x, w1.y, w1.z, w1.w,
                                     w2.x, w2.y, w2.z, w2.w};
                #pragma unroll
                for (int px = 0; px < 4; px++)
                    #pragma unroll
                    for (int dx = 0; dx < 9; dx++)
                        acc[q][px][dx] = fmaf(av[px], w[px + dx], acc[q][px][dx]);
            }
        }
    }

    // ---- write 27 displacement channels (this dy group), float4 over px
    #pragma unroll
    for (int q = 0; q < NDY; q++) {
        const int dy = 3 * g + q;
        #pragma unroll
        for (int dx = 0; dx < 9; dx++) {
            const int d = dy * 9 + dx;
            float4 v;
            float s;
            s = acc[q][0][dx] * inv_c; v.x = (s > 0.f) ? s : 0.1f * s;
            s = acc[q][1][dx] * inv_c; v.y = (s > 0.f) ? s : 0.1f * s;
            s = acc[q][2][dx] * inv_c; v.z = (s > 0.f) ? s : 0.1f * s;
            s = acc[q][3][dx] * inv_c; v.w = (s > 0.f) ? s : 0.1f * s;
            *(float4*)(out + (((size_t)n * 81 + d) * HH + y) * WW + xb) = v;
        }
    }
}

extern "C" void kernel_launch(void* const* d_in, const int* in_sizes, int n_in,
                              void* d_out, int out_size)
{
    const float* feat1 = (const float*)d_in[0];
    const float* feat2 = (const float*)d_in[1];
    float* out = (float*)d_out;

    dim3 block(8, 16, 1);                  // 128 threads
    dim3 grid(WW / 32, (HH / TY) * 3, NN); // (5, 15, 8) = 600 blocks
    corr_kernel<<<grid, block>>>(feat1, feat2, out);
}

// round 5
// speedup vs baseline: 2.4491x; 2.4491x over previous
#include <cuda_runtime.h>
#include <cuda_bf16.h>
#include <cstdint>

// PWC-Net 9x9 correlation + LeakyReLU(0.1), fp32.
// feat1, feat2: [8, 256, 80, 160]; out: [8, 81, 80, 160]
// out[n, dy*9+dx, y, x] = leaky( (1/256) * sum_c f1[n,c,y,x] * f2pad[n,c,y+dy,x+dx] )
//
// Each block: 32x16 pixel tile, one batch n, one dy-group g (3 dy values, 27 out ch).
// f1 lives in registers (thread-private). f2 window tile double-buffered in smem,
// filled with cp.async (zfill for the zero pad), prefetched one chunk ahead.

#define NN 8
#define CC 256
#define HH 80
#define WW 160
#define HW (HH * WW)
#define KC 8                     // channels per chunk
#define NCHUNK (CC / KC)         // 32
#define TY 16
#define NDY 3
#define F2ROWS (TY + NDY - 1)    // 18
#define F2PITCH 40               // 32 + 8 halo
#define BUFWORDS (KC * F2ROWS * F2PITCH)   // 5760 floats = 23040 B per buffer
#define NSLOT 12                 // max cp.async float4 slots per thread (1440/128 = 11.25)

__device__ __forceinline__ void cp_async16(uint32_t dst, const float* src, int src_size) {
    asm volatile("cp.async.cg.shared.global [%0], [%1], 16, %2;\n"
                 :: "r"(dst), "l"(src), "r"(src_size));
}

__global__ __launch_bounds__(128)
void corr_kernel(const float* __restrict__ f1,
                 const float* __restrict__ f2,
                 float* __restrict__ out)
{
    __shared__ float f2s[2 * BUFWORDS];   // 46 KB, double-buffered

    const int tx = threadIdx.x;            // 0..7
    const int ty = threadIdx.y;            // 0..15
    const int t  = ty * 8 + tx;

    const int x0 = blockIdx.x * 32;
    const int g  = blockIdx.y % 3;
    const int y0 = (blockIdx.y / 3) * TY;
    const int n  = blockIdx.z;

    const float* f1n = f1 + (size_t)n * CC * HW;
    const float* f2n = f2 + (size_t)n * CC * HW;

    const int y  = y0 + ty;
    const int xb = x0 + tx * 4;
    const int ybase = y0 + 3 * g - 4;      // global f2 row for smem r=0

    // ---- precompute per-thread cp.async slots (same pattern every chunk)
    uint32_t smem_base = (uint32_t)__cvta_generic_to_shared(f2s);
    uint32_t dst0[NSLOT];      // smem byte address in buffer 0
    uint32_t soff[NSLOT];      // word offset within one KC-channel chunk
    uint32_t amask = 0, fmask = 0;
    #pragma unroll
    for (int s = 0; s < NSLOT; s++) {
        int k = t + s * 128;
        if (k < KC * F2ROWS * 10) {        // 1440 slots
            amask |= 1u << s;
            int c   = k / (F2ROWS * 10);
            int rem = k - c * (F2ROWS * 10);
            int r   = rem / 10;
            int i4  = rem - r * 10;
            int gy  = ybase + r;
            int gx  = x0 - 4 + i4 * 4;
            bool in = (gy >= 0 && gy < HH && gx >= 0 && gx + 3 < WW);
            if (in) fmask |= 1u << s;
            int cgy = in ? gy : 0;
            int cgx = in ? gx : 0;
            soff[s] = (uint32_t)(c * HH + cgy) * WW + cgx;
            dst0[s] = smem_base + (uint32_t)((c * F2ROWS + r) * F2PITCH + i4 * 4) * 4u;
        }
    }

    // ---- accumulators
    float acc[NDY][4][9];
    #pragma unroll
    for (int q = 0; q < NDY; q++)
        #pragma unroll
        for (int px = 0; px < 4; px++)
            #pragma unroll
            for (int dx = 0; dx < 9; dx++)
                acc[q][px][dx] = 0.0f;

    // ---- prologue: fill buffer 0 with chunk 0
    #pragma unroll
    for (int s = 0; s < NSLOT; s++) {
        if ((amask >> s) & 1) {
            int sz = ((fmask >> s) & 1) ? 16 : 0;
            cp_async16(dst0[s], f2n + soff[s], sz);
        }
    }
    asm volatile("cp.async.commit_group;\n" ::);

    const float* f1p = f1n + (size_t)y * WW + xb;   // advances by KC*HW per chunk

    for (int i = 0; i < NCHUNK; i++) {
        const int b = i & 1;
        const uint32_t bufbyte = (uint32_t)(b ^ 1) * (BUFWORDS * 4);
        const int boff = b * BUFWORDS;

        __syncthreads();   // all warps done computing on buffer (b^1) from iter i-1

        if (i + 1 < NCHUNK) {
            const float* src = f2n + (size_t)(i + 1) * KC * HW;
            #pragma unroll
            for (int s = 0; s < NSLOT; s++) {
                if ((amask >> s) & 1) {
                    int sz = ((fmask >> s) & 1) ? 16 : 0;
                    cp_async16(dst0[s] + bufbyte, src + soff[s], sz);
                }
            }
            asm volatile("cp.async.commit_group;\n" ::);
            asm volatile("cp.async.wait_group 1;\n" ::);  // chunk i (buffer b) done
        } else {
            asm volatile("cp.async.wait_group 0;\n" ::);
        }

        __syncthreads();   // all threads' fills of buffer b visible

        // f1 for this chunk: 8 coalesced LDG.128, front-batched for MLP
        float4 a[KC];
        #pragma unroll
        for (int c = 0; c < KC; c++)
            a[c] = *(const float4*)(f1p + (size_t)c * HW);

        #pragma unroll
        for (int c = 0; c < KC; c++) {
            const float av[4] = {a[c].x, a[c].y, a[c].z, a[c].w};
            #pragma unroll
            for (int q = 0; q < NDY; q++) {
                const float* wr = &f2s[boff + (c * F2ROWS + ty + q) * F2PITCH + tx * 4];
                const float4 w0 = *(const float4*)(wr);
                const float4 w1 = *(const float4*)(wr + 4);
                const float4 w2 = *(const float4*)(wr + 8);
                const float w[12] = {w0.x, w0.y, w0.z, w0.w,
                                     w1.x, w1.y, w1.z, w1.w,
                                     w2.x, w2.y, w2.z, w2.w};
                #pragma unroll
                for (int px = 0; px < 4; px++)
                    #pragma unroll
                    for (int dx = 0; dx < 9; dx++)
                        acc[q][px][dx] = fmaf(av[px], w[px + dx], acc[q][px][dx]);
            }
        }

        f1p += (size_t)KC * HW;
    }

    // ---- epilogue: 27 output channels, float4 over px
    const float inv_c = 1.0f / 256.0f;
    #pragma unroll
    for (int q = 0; q < NDY; q++) {
        const int dy = 3 * g + q;
        #pragma unroll
        for (int dx = 0; dx < 9; dx++) {
            const int d = dy * 9 + dx;
            float4 v;
            float s;
            s = acc[q][0][dx] * inv_c; v.x = (s > 0.f) ? s : 0.1f * s;
            s = acc[q][1][dx] * inv_c; v.y = (s > 0.f) ? s : 0.1f * s;
            s = acc[q][2][dx] * inv_c; v.z = (s > 0.f) ? s : 0.1f * s;
            s = acc[q][3][dx] * inv_c; v.w = (s > 0.f) ? s : 0.1f * s;
            *(float4*)(out + (((size_t)n * 81 + d) * HH + y) * WW + xb) = v;
        }
    }
}

extern "C" void kernel_launch(void* const* d_in, const int* in_sizes, int n_in,
                              void* d_out, int out_size)
{
    const float* feat1 = (const float*)d_in[0];
    const float* feat2 = (const float*)d_in[1];
    float* out = (float*)d_out;

    dim3 block(8, 16, 1);                  // 128 threads
    dim3 grid(WW / 32, (HH / TY) * 3, NN); // (5, 15, 8) = 600 blocks
    corr_kernel<<<grid, block>>>(feat1, feat2, out);
}